// round 2
// baseline (speedup 1.0000x reference)
#include <cuda_runtime.h>
#include <cstdint>

#define BB 1024
#define SS 200
#define DD 64
#define NI 4
#define EE 256   // NI*DD

// ---------------- scratch (device globals; no allocations allowed) ----------
__device__ float g_up[BB * DD];                    // user profile (B,64)
__device__ float g_ih[BB * SS * DD];               // item_his (B,200,64)  52.4MB
__device__ float g_hat[BB * NI * SS * DD];         // hat in (B,K,S,D)    209.7MB

// ---------------- prep: user profile -----------------------------------------
__global__ void k_prep_up(const int* __restrict__ uid, const int* __restrict__ age,
                          const int* __restrict__ gender, const int* __restrict__ occup,
                          const float* __restrict__ ut, const float* __restrict__ at,
                          const float* __restrict__ gt, const float* __restrict__ ot) {
    int idx = blockIdx.x * blockDim.x + threadIdx.x;
    if (idx >= BB * DD) return;
    int b = idx >> 6, d = idx & 63;
    g_up[idx] = 0.25f * (ut[uid[b] * 64 + d] + gt[gender[b] * 64 + d] +
                         at[age[b] * 64 + d] + ot[occup[b] * 64 + d]);
}

// ---------------- prep: item_his = mid_emb[mid_his] * mask -------------------
__global__ void k_prep_ih(const int* __restrict__ mid, const float* __restrict__ mask,
                          const float* __restrict__ memb) {
    int idx = blockIdx.x * blockDim.x + threadIdx.x;   // over B*S*16 float4s
    if (idx >= BB * SS * 16) return;
    int bs = idx >> 4, f = idx & 15;
    float m = mask[bs];
    int row = mid[bs];
    float4 v = ((const float4*)memb)[row * 16 + f];
    float4 o; o.x = v.x * m; o.y = v.y * m; o.z = v.z * m; o.w = v.w * m;
    ((float4*)g_ih)[idx] = o;
}

// ---------------- adj: sigmoid((ih*up) @ ih^T) * mask_outer -------------------
// one CTA per batch element; ih & hu tiles resident in smem (stride 65 = pad)
#define ADJ_SMEM ((2 * 200 * 65 + 256) * 4)
__global__ void __launch_bounds__(256) k_adj(const float* __restrict__ mask,
                                             float* __restrict__ out_adj) {
    extern __shared__ float sm[];
    float* s_ih   = sm;              // [200][65]
    float* s_hu   = sm + 13000;      // [200][65]
    float* s_mask = sm + 26000;      // [200]
    int b = blockIdx.x;
    int tid = threadIdx.x;

    const float4* ih4 = ((const float4*)g_ih) + b * 200 * 16;
    const float4* up4 = ((const float4*)g_up) + b * 16;
    for (int idx = tid; idx < 200 * 16; idx += 256) {
        int s = idx >> 4, f = idx & 15;
        float4 v = ih4[idx];
        float4 u = up4[f];
        int base = s * 65 + f * 4;
        s_ih[base + 0] = v.x; s_ih[base + 1] = v.y;
        s_ih[base + 2] = v.z; s_ih[base + 3] = v.w;
        s_hu[base + 0] = v.x * u.x; s_hu[base + 1] = v.y * u.y;
        s_hu[base + 2] = v.z * u.z; s_hu[base + 3] = v.w * u.w;
    }
    if (tid < 200) s_mask[tid] = mask[b * 200 + tid];
    __syncthreads();

    int tx = tid & 15, ty = tid >> 4;
    float* outb = out_adj + (size_t)b * 40000;

    for (int tj0 = 0; tj0 < 256; tj0 += 64)
    for (int ti0 = 0; ti0 < 256; ti0 += 64) {
        int i0 = ti0 + ty;     // rows i0 + 16*r
        int j0 = tj0 + tx;     // cols j0 + 16*c
        if (i0 >= 200 || j0 >= 200) continue;

        int ii[4], jj[4];
        bool iv[4], jv[4];
        #pragma unroll
        for (int r = 0; r < 4; r++) { int i = i0 + 16 * r; iv[r] = (i < 200); ii[r] = iv[r] ? i : 0; }
        #pragma unroll
        for (int c = 0; c < 4; c++) { int j = j0 + 16 * c; jv[c] = (j < 200); jj[c] = jv[c] ? j : 0; }

        float acc[4][4];
        #pragma unroll
        for (int r = 0; r < 4; r++)
            #pragma unroll
            for (int c = 0; c < 4; c++) acc[r][c] = 0.f;

        #pragma unroll 8
        for (int k = 0; k < 64; k++) {
            float a[4], bv[4];
            #pragma unroll
            for (int r = 0; r < 4; r++) a[r] = s_hu[ii[r] * 65 + k];
            #pragma unroll
            for (int c = 0; c < 4; c++) bv[c] = s_ih[jj[c] * 65 + k];
            #pragma unroll
            for (int r = 0; r < 4; r++)
                #pragma unroll
                for (int c = 0; c < 4; c++) acc[r][c] += a[r] * bv[c];
        }

        #pragma unroll
        for (int r = 0; r < 4; r++) if (iv[r]) {
            float mi = s_mask[ii[r]];
            #pragma unroll
            for (int c = 0; c < 4; c++) if (jv[c]) {
                float v = 1.f / (1.f + __expf(-acc[r][c]));
                outb[ii[r] * 200 + jj[c]] = v * mi * s_mask[jj[c]];
            }
        }
    }
}

// ---------------- hat: per-s GEMM [128,64] @ [64,256]^T ----------------------
// grid (s=200, bt=8), 512 threads. W transposed to [k][e] (stride 257),
// A transposed to [k][b] (stride 129). Lane-consecutive e => conflict-free.
#define HAT_SMEM ((64 * 257 + 64 * 129) * 4)
__global__ void __launch_bounds__(512) k_hat(const float* __restrict__ wcap) {
    extern __shared__ float sm[];
    float* sW = sm;             // [64][257]
    float* sA = sm + 64 * 257;  // [64][129]
    int s  = blockIdx.x;
    int bt = blockIdx.y;
    int tid = threadIdx.x;

    const float4* w4 = ((const float4*)wcap) + s * EE * 16;
    for (int idx = tid; idx < 256 * 16; idx += 512) {
        int e = idx >> 4, f = idx & 15;
        float4 v = w4[idx];
        int k = f * 4;
        sW[(k + 0) * 257 + e] = v.x;
        sW[(k + 1) * 257 + e] = v.y;
        sW[(k + 2) * 257 + e] = v.z;
        sW[(k + 3) * 257 + e] = v.w;
    }
    const float4* ih4 = (const float4*)g_ih;
    for (int idx = tid; idx < 128 * 16; idx += 512) {
        int r = idx >> 4, f = idx & 15;
        float4 v = ih4[((bt * 128 + r) * 200 + s) * 16 + f];
        int k = f * 4;
        sA[(k + 0) * 129 + r] = v.x;
        sA[(k + 1) * 129 + r] = v.y;
        sA[(k + 2) * 129 + r] = v.z;
        sA[(k + 3) * 129 + r] = v.w;
    }
    __syncthreads();

    int lane = tid & 31, tB = tid >> 5;
    int b0 = tB * 8;
    float acc[8][8];
    #pragma unroll
    for (int j = 0; j < 8; j++)
        #pragma unroll
        for (int i = 0; i < 8; i++) acc[j][i] = 0.f;

    #pragma unroll 4
    for (int k = 0; k < 64; k++) {
        float w[8], a[8];
        #pragma unroll
        for (int j = 0; j < 8; j++) w[j] = sW[k * 257 + lane + 32 * j];
        #pragma unroll
        for (int i = 0; i < 8; i++) a[i] = sA[k * 129 + b0 + i];
        #pragma unroll
        for (int j = 0; j < 8; j++)
            #pragma unroll
            for (int i = 0; i < 8; i++) acc[j][i] += w[j] * a[i];
    }

    int bbase = bt * 128 + b0;
    #pragma unroll
    for (int j = 0; j < 8; j++) {
        int kk = j >> 1;
        int dd = (j & 1) * 32 + lane;
        #pragma unroll
        for (int i = 0; i < 8; i++) {
            int b = bbase + i;
            g_hat[((b * 4 + kk) * 200 + s) * 64 + dd] = acc[j][i];
        }
    }
}

// ---------------- routing: 3 dynamic-routing iterations, hat[b] in smem ------
#define ROUT_SMEM ((51200 + 800 + 800 + 256 + 256 + 208) * 4)
__global__ void __launch_bounds__(256) k_route(const float* __restrict__ mask,
                                               float* __restrict__ out_cap) {
    extern __shared__ float sm[];
    float* s_hat  = sm;               // [4][200][64]
    float* s_cw   = sm + 51200;       // [4][200]
    float* s_sw   = s_cw + 800;       // [4][200]
    float* s_cap  = s_sw + 800;       // [4][64]
    float* s_cq   = s_cap + 256;      // [4][64]
    float* s_mask = s_cq + 256;       // [200]
    int b = blockIdx.x, tid = threadIdx.x;

    const float4* h4 = (const float4*)(g_hat + (size_t)b * 51200);
    float4* sh4 = (float4*)s_hat;
    for (int i = tid; i < 12800; i += 256) sh4[i] = h4[i];
    for (int i = tid; i < 800; i += 256) s_cw[i] = 0.f;
    if (tid < 200) s_mask[tid] = mask[b * 200 + tid];
    __syncthreads();

    int k = tid >> 6, d = tid & 63;
    int lane = tid & 31, w = tid >> 5;

    for (int it = 0; it < 3; it++) {
        if (tid < 200) {
            float c0 = s_cw[tid],       c1 = s_cw[200 + tid];
            float c2 = s_cw[400 + tid], c3 = s_cw[600 + tid];
            float m = fmaxf(fmaxf(c0, c1), fmaxf(c2, c3));
            float e0 = __expf(c0 - m), e1 = __expf(c1 - m);
            float e2 = __expf(c2 - m), e3 = __expf(c3 - m);
            float inv = 1.f / (e0 + e1 + e2 + e3);
            float mk = s_mask[tid];
            if (mk == 0.f) {
                s_sw[tid] = 0.f; s_sw[200 + tid] = 0.f;
                s_sw[400 + tid] = 0.f; s_sw[600 + tid] = 0.f;
            } else {
                s_sw[tid] = e0 * inv; s_sw[200 + tid] = e1 * inv;
                s_sw[400 + tid] = e2 * inv; s_sw[600 + tid] = e3 * inv;
            }
        }
        __syncthreads();

        // cap[k][d] = sum_s sw[k][s] * hat[k][s][d]
        float acc = 0.f;
        const float* hk = s_hat + (k * 200) * 64 + d;
        const float* swk = s_sw + k * 200;
        #pragma unroll 4
        for (int s = 0; s < 200; s++) acc += swk[s] * hk[s * 64];
        s_cap[tid] = acc;
        __syncthreads();

        // squash (redundant per-thread reduction over 64 d's of own k)
        float n = 0.f;
        const float* ck = s_cap + k * 64;
        #pragma unroll 8
        for (int dd = 0; dd < 64; dd++) { float v = ck[dd]; n += v * v; }
        float scale = n / (1.f + n) * rsqrtf(n + 1e-9f);
        float cq = acc * scale;

        if (it == 2) {
            out_cap[b * 256 + tid] = cq;
        } else {
            s_cq[tid] = cq;
            __syncthreads();
            // delta[k][s] = dot(hat[k][s][:], cq[k][:]);  cw += delta
            for (int p = w; p < 800; p += 8) {
                int kk = p / 200, ss = p % 200;
                const float* hr = s_hat + (kk * 200 + ss) * 64;
                float v = hr[lane] * s_cq[kk * 64 + lane] +
                          hr[32 + lane] * s_cq[kk * 64 + 32 + lane];
                v += __shfl_xor_sync(0xffffffffu, v, 16);
                v += __shfl_xor_sync(0xffffffffu, v, 8);
                v += __shfl_xor_sync(0xffffffffu, v, 4);
                v += __shfl_xor_sync(0xffffffffu, v, 2);
                v += __shfl_xor_sync(0xffffffffu, v, 1);
                if (lane == 0) s_cw[kk * 200 + ss] += v;
            }
            __syncthreads();
        }
    }
}

// ---------------- launcher ----------------------------------------------------
extern "C" void kernel_launch(void* const* d_in, const int* in_sizes, int n_in,
                              void* d_out, int out_size) {
    const int*   uid    = (const int*)d_in[0];
    const int*   age    = (const int*)d_in[1];
    const int*   gender = (const int*)d_in[2];
    const int*   occup  = (const int*)d_in[3];
    const int*   mid    = (const int*)d_in[4];
    const float* mask   = (const float*)d_in[5];
    const float* ut     = (const float*)d_in[6];
    const float* at     = (const float*)d_in[7];
    const float* gt     = (const float*)d_in[8];
    const float* ot     = (const float*)d_in[9];
    const float* memb   = (const float*)d_in[10];
    const float* wcap   = (const float*)d_in[11];

    float* out_cap = (float*)d_out;                      // (B, NI, D)
    float* out_adj = (float*)d_out + BB * NI * DD;       // (B, S, S)

    static bool attrs_set = false;
    if (!attrs_set) {
        cudaFuncSetAttribute(k_adj,   cudaFuncAttributeMaxDynamicSharedMemorySize, ADJ_SMEM);
        cudaFuncSetAttribute(k_hat,   cudaFuncAttributeMaxDynamicSharedMemorySize, HAT_SMEM);
        cudaFuncSetAttribute(k_route, cudaFuncAttributeMaxDynamicSharedMemorySize, ROUT_SMEM);
        attrs_set = true;
    }

    k_prep_up<<<(BB * DD + 255) / 256, 256>>>(uid, age, gender, occup, ut, at, gt, ot);
    k_prep_ih<<<(BB * SS * 16 + 255) / 256, 256>>>(mid, mask, memb);
    k_adj<<<BB, 256, ADJ_SMEM>>>(mask, out_adj);
    k_hat<<<dim3(SS, 8), 512, HAT_SMEM>>>(wcap);
    k_route<<<BB, 256, ROUT_SMEM>>>(mask, out_cap);
}

// round 6
// speedup vs baseline: 1.1010x; 1.1010x over previous
#include <cuda_runtime.h>
#include <cstdint>

#define BB 1024
#define SS 200
#define DD 64
#define NI 4
#define EE 256   // NI*DD
#define ST 68    // smem row stride (floats): 68 mod 32 = 4 -> conflict-free frag loads

// ================= mma.sync tf32 helpers =====================================
__device__ __forceinline__ uint32_t f2tf(float f) {
    uint32_t r; asm("cvt.rna.tf32.f32 %0, %1;" : "=r"(r) : "f"(f)); return r;
}
__device__ __forceinline__ void mma_tf32(float* c, const uint32_t* a, uint32_t b0, uint32_t b1) {
    asm volatile("mma.sync.aligned.m16n8k8.row.col.f32.tf32.tf32.f32 "
        "{%0,%1,%2,%3}, {%4,%5,%6,%7}, {%8,%9}, {%0,%1,%2,%3};"
        : "+f"(c[0]), "+f"(c[1]), "+f"(c[2]), "+f"(c[3])
        : "r"(a[0]), "r"(a[1]), "r"(a[2]), "r"(a[3]), "r"(b0), "r"(b1));
}

// ================= scratch ====================================================
__device__ float g_up[BB * DD];
__device__ float g_ih[BB * SS * DD];
__device__ float g_hat[BB * NI * SS * DD];

// ================= prep =======================================================
__global__ void k_prep_up(const int* __restrict__ uid, const int* __restrict__ age,
                          const int* __restrict__ gender, const int* __restrict__ occup,
                          const float* __restrict__ ut, const float* __restrict__ at,
                          const float* __restrict__ gt, const float* __restrict__ ot) {
    int idx = blockIdx.x * blockDim.x + threadIdx.x;
    if (idx >= BB * DD) return;
    int b = idx >> 6, d = idx & 63;
    g_up[idx] = 0.25f * (ut[uid[b] * 64 + d] + gt[gender[b] * 64 + d] +
                         at[age[b] * 64 + d] + ot[occup[b] * 64 + d]);
}

__global__ void k_prep_ih(const int* __restrict__ mid, const float* __restrict__ mask,
                          const float* __restrict__ memb) {
    int idx = blockIdx.x * blockDim.x + threadIdx.x;
    if (idx >= BB * SS * 16) return;
    int bs = idx >> 4, f = idx & 15;
    float m = mask[bs];
    int row = mid[bs];
    float4 v = ((const float4*)memb)[row * 16 + f];
    float4 o; o.x = v.x * m; o.y = v.y * m; o.z = v.z * m; o.w = v.w * m;
    ((float4*)g_ih)[idx] = o;
}

// ================= adj: sigmoid((ih*up) @ ih^T) * mask_outer ==================
// one CTA per b, 256 thr (8 warps). A=hu (rows i), B=ih (rows j), K=64.
// warp tiles 32x32, 7x7=49 tiles cover 224x224 (>=200).
#define ADJ_SMEM ((224 * ST * 2 + 224) * 4)
__global__ void __launch_bounds__(256) k_adj(const float* __restrict__ mask,
                                             float* __restrict__ out_adj) {
    extern __shared__ float sm[];
    float* s_hu   = sm;                 // [224][ST]
    float* s_ih   = sm + 224 * ST;      // [224][ST]
    float* s_mask = sm + 448 * ST;      // [224]
    int b = blockIdx.x, tid = threadIdx.x;

    const float4* ih4 = ((const float4*)g_ih) + (size_t)b * 200 * 16;
    const float4* up4 = ((const float4*)g_up) + b * 16;
    for (int idx = tid; idx < 224 * 16; idx += 256) {
        int r = idx >> 4, f = idx & 15;
        float4 v = (r < 200) ? ih4[r * 16 + f] : make_float4(0.f, 0.f, 0.f, 0.f);
        float4 u = up4[f];
        int base = r * ST + f * 4;
        s_ih[base + 0] = v.x; s_ih[base + 1] = v.y;
        s_ih[base + 2] = v.z; s_ih[base + 3] = v.w;
        s_hu[base + 0] = v.x * u.x; s_hu[base + 1] = v.y * u.y;
        s_hu[base + 2] = v.z * u.z; s_hu[base + 3] = v.w * u.w;
    }
    if (tid < 224) s_mask[tid] = (tid < 200) ? mask[b * 200 + tid] : 0.f;
    __syncthreads();

    int wid = tid >> 5, lane = tid & 31, g = lane >> 2, q = lane & 3;
    float* outb = out_adj + (size_t)b * 40000;

    for (int t = wid; t < 49; t += 8) {
        int R = (t / 7) * 32, C = (t % 7) * 32;
        float c[2][4][4];
        #pragma unroll
        for (int mf = 0; mf < 2; mf++)
            #pragma unroll
            for (int nf = 0; nf < 4; nf++)
                #pragma unroll
                for (int x = 0; x < 4; x++) c[mf][nf][x] = 0.f;

        #pragma unroll 2
        for (int k0 = 0; k0 < 64; k0 += 8) {
            uint32_t A[2][4];
            #pragma unroll
            for (int mf = 0; mf < 2; mf++) {
                const float* p = s_hu + (R + mf * 16 + g) * ST + k0 + q;
                A[mf][0] = f2tf(p[0]);
                A[mf][1] = f2tf(p[8 * ST]);
                A[mf][2] = f2tf(p[4]);
                A[mf][3] = f2tf(p[8 * ST + 4]);
            }
            #pragma unroll
            for (int nf = 0; nf < 4; nf++) {
                const float* p = s_ih + (C + nf * 8 + g) * ST + k0 + q;
                uint32_t b0 = f2tf(p[0]), b1 = f2tf(p[4]);
                mma_tf32(c[0][nf], A[0], b0, b1);
                mma_tf32(c[1][nf], A[1], b0, b1);
            }
        }

        #pragma unroll
        for (int mf = 0; mf < 2; mf++)
            #pragma unroll
            for (int sub = 0; sub < 2; sub++) {
                int i = R + mf * 16 + g + sub * 8;
                if (i < 200) {
                    float mi = s_mask[i];
                    #pragma unroll
                    for (int nf = 0; nf < 4; nf++) {
                        int j = C + nf * 8 + 2 * q;
                        if (j < 200) {
                            float v0 = mi * s_mask[j]     / (1.f + __expf(-c[mf][nf][sub * 2 + 0]));
                            float v1 = mi * s_mask[j + 1] / (1.f + __expf(-c[mf][nf][sub * 2 + 1]));
                            *(float2*)(outb + i * 200 + j) = make_float2(v0, v1);
                        }
                    }
                }
            }
    }
}

// ================= hat: hat[b][e] = ih[b,s,:] . W[s,e,:] ======================
// grid (bt=8, s=200), 256 thr. A=ih (m=b, 128), B=W (n=e, 256), K=64.
// warp tiles 32x32: 4x8=32 tiles.
#define HAT_SMEM ((128 * ST + 256 * ST) * 4)
__global__ void __launch_bounds__(256) k_hat(const float* __restrict__ wcap) {
    extern __shared__ float sm[];
    float* s_a = sm;               // ih [128][ST]
    float* s_w = sm + 128 * ST;    // W  [256][ST]
    int bt = blockIdx.x, s = blockIdx.y;
    int tid = threadIdx.x;

    const float4* ih4 = (const float4*)g_ih;
    for (int idx = tid; idx < 128 * 16; idx += 256) {
        int r = idx >> 4, f = idx & 15;
        float4 v = ih4[((size_t)(bt * 128 + r) * 200 + s) * 16 + f];
        int base = r * ST + f * 4;
        s_a[base + 0] = v.x; s_a[base + 1] = v.y;
        s_a[base + 2] = v.z; s_a[base + 3] = v.w;
    }
    const float4* w4 = ((const float4*)wcap) + (size_t)s * EE * 16;
    for (int idx = tid; idx < 256 * 16; idx += 256) {
        int r = idx >> 4, f = idx & 15;
        float4 v = w4[idx];
        int base = r * ST + f * 4;
        s_w[base + 0] = v.x; s_w[base + 1] = v.y;
        s_w[base + 2] = v.z; s_w[base + 3] = v.w;
    }
    __syncthreads();

    int wid = tid >> 5, lane = tid & 31, g = lane >> 2, q = lane & 3;

    for (int t = wid; t < 32; t += 8) {
        int R = (t & 3) * 32;       // b-local base
        int C = (t >> 2) * 32;      // e base
        float c[2][4][4];
        #pragma unroll
        for (int mf = 0; mf < 2; mf++)
            #pragma unroll
            for (int nf = 0; nf < 4; nf++)
                #pragma unroll
                for (int x = 0; x < 4; x++) c[mf][nf][x] = 0.f;

        #pragma unroll 2
        for (int k0 = 0; k0 < 64; k0 += 8) {
            uint32_t A[2][4];
            #pragma unroll
            for (int mf = 0; mf < 2; mf++) {
                const float* p = s_a + (R + mf * 16 + g) * ST + k0 + q;
                A[mf][0] = f2tf(p[0]);
                A[mf][1] = f2tf(p[8 * ST]);
                A[mf][2] = f2tf(p[4]);
                A[mf][3] = f2tf(p[8 * ST + 4]);
            }
            #pragma unroll
            for (int nf = 0; nf < 4; nf++) {
                const float* p = s_w + (C + nf * 8 + g) * ST + k0 + q;
                uint32_t b0 = f2tf(p[0]), b1 = f2tf(p[4]);
                mma_tf32(c[0][nf], A[0], b0, b1);
                mma_tf32(c[1][nf], A[1], b0, b1);
            }
        }

        #pragma unroll
        for (int mf = 0; mf < 2; mf++)
            #pragma unroll
            for (int sub = 0; sub < 2; sub++) {
                int b_g = bt * 128 + R + mf * 16 + g + sub * 8;
                #pragma unroll
                for (int nf = 0; nf < 4; nf++) {
                    int e = C + nf * 8 + 2 * q;
                    int kk = e >> 6, dd = e & 63;
                    float2 v = make_float2(c[mf][nf][sub * 2 + 0], c[mf][nf][sub * 2 + 1]);
                    *(float2*)(g_hat + (((size_t)b_g * 4 + kk) * 200 + s) * 64 + dd) = v;
                }
            }
    }
}

// ================= routing: 512 threads, split cap-sum ========================
#define ROUT_SMEM ((51200 + 800 + 800 + 256 + 256 + 224 + 512) * 4)
__global__ void __launch_bounds__(512) k_route(const float* __restrict__ mask,
                                               float* __restrict__ out_cap) {
    extern __shared__ float sm[];
    float* s_hat  = sm;               // [4][200][64]
    float* s_cw   = sm + 51200;       // [4][200]
    float* s_sw   = s_cw + 800;       // [4][200]
    float* s_cap  = s_sw + 800;       // [4][64]
    float* s_cq   = s_cap + 256;      // [4][64]
    float* s_mask = s_cq + 256;       // [224]
    float* s_red  = s_mask + 224;     // [512]
    int b = blockIdx.x, tid = threadIdx.x;

    const float4* h4 = (const float4*)(g_hat + (size_t)b * 51200);
    float4* sh4 = (float4*)s_hat;
    for (int i = tid; i < 12800; i += 512) sh4[i] = h4[i];
    for (int i = tid; i < 800; i += 512) s_cw[i] = 0.f;
    if (tid < 200) s_mask[tid] = mask[b * 200 + tid];
    __syncthreads();

    int kd = tid & 255, half = tid >> 8;
    int k = kd >> 6, d = kd & 63;
    int lane = tid & 31, w = tid >> 5;

    for (int it = 0; it < 3; it++) {
        if (tid < 200) {
            float c0 = s_cw[tid],       c1 = s_cw[200 + tid];
            float c2 = s_cw[400 + tid], c3 = s_cw[600 + tid];
            float m = fmaxf(fmaxf(c0, c1), fmaxf(c2, c3));
            float e0 = __expf(c0 - m), e1 = __expf(c1 - m);
            float e2 = __expf(c2 - m), e3 = __expf(c3 - m);
            float inv = 1.f / (e0 + e1 + e2 + e3);
            float mk = s_mask[tid];
            if (mk == 0.f) {
                s_sw[tid] = 0.f; s_sw[200 + tid] = 0.f;
                s_sw[400 + tid] = 0.f; s_sw[600 + tid] = 0.f;
            } else {
                s_sw[tid] = e0 * inv; s_sw[200 + tid] = e1 * inv;
                s_sw[400 + tid] = e2 * inv; s_sw[600 + tid] = e3 * inv;
            }
        }
        __syncthreads();

        // cap[k][d] = sum_s sw[k][s] * hat[k][s][d] — split over 2 halves of s
        float acc = 0.f;
        {
            const float* hk  = s_hat + (k * 200 + half * 100) * 64 + d;
            const float* swk = s_sw + k * 200 + half * 100;
            #pragma unroll 4
            for (int s = 0; s < 100; s++) acc += swk[s] * hk[s * 64];
        }
        s_red[tid] = acc;
        __syncthreads();

        float cq = 0.f;
        if (half == 0) {
            float capv = s_red[tid] + s_red[tid + 256];
            s_cap[kd] = capv;
        }
        __syncthreads();
        if (half == 0) {
            float n = 0.f;
            const float* ck = s_cap + k * 64;
            #pragma unroll 8
            for (int dd = 0; dd < 64; dd++) { float v = ck[dd]; n += v * v; }
            float scale = n / (1.f + n) * rsqrtf(n + 1e-9f);
            cq = s_cap[kd] * scale;
            if (it == 2) out_cap[b * 256 + kd] = cq;
            else         s_cq[kd] = cq;
        }

        if (it < 2) {
            __syncthreads();
            // delta[k][s] = dot(hat[k][s][:], cq[k][:]);  cw += delta — 16 warps
            for (int p = w; p < 800; p += 16) {
                int kk = p / 200, ss = p % 200;
                const float* hr = s_hat + (kk * 200 + ss) * 64;
                float v = hr[lane] * s_cq[kk * 64 + lane] +
                          hr[32 + lane] * s_cq[kk * 64 + 32 + lane];
                v += __shfl_xor_sync(0xffffffffu, v, 16);
                v += __shfl_xor_sync(0xffffffffu, v, 8);
                v += __shfl_xor_sync(0xffffffffu, v, 4);
                v += __shfl_xor_sync(0xffffffffu, v, 2);
                v += __shfl_xor_sync(0xffffffffu, v, 1);
                if (lane == 0) s_cw[kk * 200 + ss] += v;
            }
            __syncthreads();
        }
    }
}

// ================= launcher ===================================================
extern "C" void kernel_launch(void* const* d_in, const int* in_sizes, int n_in,
                              void* d_out, int out_size) {
    const int*   uid    = (const int*)d_in[0];
    const int*   age    = (const int*)d_in[1];
    const int*   gender = (const int*)d_in[2];
    const int*   occup  = (const int*)d_in[3];
    const int*   mid    = (const int*)d_in[4];
    const float* mask   = (const float*)d_in[5];
    const float* ut     = (const float*)d_in[6];
    const float* at     = (const float*)d_in[7];
    const float* gt     = (const float*)d_in[8];
    const float* ot     = (const float*)d_in[9];
    const float* memb   = (const float*)d_in[10];
    const float* wcap   = (const float*)d_in[11];

    float* out_cap = (float*)d_out;
    float* out_adj = (float*)d_out + BB * NI * DD;

    cudaFuncSetAttribute(k_adj,   cudaFuncAttributeMaxDynamicSharedMemorySize, ADJ_SMEM);
    cudaFuncSetAttribute(k_hat,   cudaFuncAttributeMaxDynamicSharedMemorySize, HAT_SMEM);
    cudaFuncSetAttribute(k_route, cudaFuncAttributeMaxDynamicSharedMemorySize, ROUT_SMEM);

    k_prep_up<<<(BB * DD + 255) / 256, 256>>>(uid, age, gender, occup, ut, at, gt, ot);
    k_prep_ih<<<(BB * SS * 16 + 255) / 256, 256>>>(mid, mask, memb);
    k_hat<<<dim3(8, SS), 256, HAT_SMEM>>>(wcap);
    k_adj<<<BB, 256, ADJ_SMEM>>>(mask, out_adj);
    k_route<<<BB, 512, ROUT_SMEM>>>(mask, out_cap);
}

// round 7
// speedup vs baseline: 1.5561x; 1.4133x over previous
#include <cuda_runtime.h>
#include <cstdint>

#define BB 1024
#define SS 200
#define DD 64
#define NI 4
#define EE 256   // NI*DD
#define ST 68    // smem row stride (words): 68 mod 32 = 4 -> conflict-free frag loads

// ================= mma.sync tf32 helpers =====================================
__device__ __forceinline__ uint32_t f2tf(float f) {
    uint32_t r; asm("cvt.rna.tf32.f32 %0, %1;" : "=r"(r) : "f"(f)); return r;
}
__device__ __forceinline__ void mma_tf32(float* c, const uint32_t* a, uint32_t b0, uint32_t b1) {
    asm volatile("mma.sync.aligned.m16n8k8.row.col.f32.tf32.tf32.f32 "
        "{%0,%1,%2,%3}, {%4,%5,%6,%7}, {%8,%9}, {%0,%1,%2,%3};"
        : "+f"(c[0]), "+f"(c[1]), "+f"(c[2]), "+f"(c[3])
        : "r"(a[0]), "r"(a[1]), "r"(a[2]), "r"(a[3]), "r"(b0), "r"(b1));
}

// ================= scratch ====================================================
__device__ float g_up[BB * DD];
__device__ float g_ih[BB * SS * DD];
__device__ float g_hat[BB * NI * SS * DD];

// ================= prep =======================================================
__global__ void k_prep_up(const int* __restrict__ uid, const int* __restrict__ age,
                          const int* __restrict__ gender, const int* __restrict__ occup,
                          const float* __restrict__ ut, const float* __restrict__ at,
                          const float* __restrict__ gt, const float* __restrict__ ot) {
    int idx = blockIdx.x * blockDim.x + threadIdx.x;
    if (idx >= BB * DD) return;
    int b = idx >> 6, d = idx & 63;
    g_up[idx] = 0.25f * (ut[uid[b] * 64 + d] + gt[gender[b] * 64 + d] +
                         at[age[b] * 64 + d] + ot[occup[b] * 64 + d]);
}

__global__ void k_prep_ih(const int* __restrict__ mid, const float* __restrict__ mask,
                          const float* __restrict__ memb) {
    int idx = blockIdx.x * blockDim.x + threadIdx.x;
    if (idx >= BB * SS * 16) return;
    int bs = idx >> 4, f = idx & 15;
    float m = mask[bs];
    int row = mid[bs];
    float4 v = ((const float4*)memb)[row * 16 + f];
    float4 o; o.x = v.x * m; o.y = v.y * m; o.z = v.z * m; o.w = v.w * m;
    ((float4*)g_ih)[idx] = o;
}

// ================= adj: sigmoid((ih*up) @ ih^T) * mask_outer ==================
// one CTA per b, 512 thr (16 warps). smem holds PRE-CONVERTED tf32 operands.
// warp tiles 32x32, 7x7=49 tiles cover 224x224 (>=200).
#define ADJ_SMEM ((224 * ST * 2 + 224) * 4)
__global__ void __launch_bounds__(512) k_adj(const float* __restrict__ mask,
                                             float* __restrict__ out_adj) {
    extern __shared__ uint32_t smu[];
    uint32_t* s_hu   = smu;                 // [224][ST] tf32
    uint32_t* s_ih   = smu + 224 * ST;      // [224][ST] tf32
    float*    s_mask = (float*)(smu + 448 * ST);   // [224]
    int b = blockIdx.x, tid = threadIdx.x;

    const float4* ih4 = ((const float4*)g_ih) + (size_t)b * 200 * 16;
    const float4* up4 = ((const float4*)g_up) + b * 16;
    for (int idx = tid; idx < 224 * 16; idx += 512) {
        int r = idx >> 4, f = idx & 15;
        float4 v = (r < 200) ? ih4[r * 16 + f] : make_float4(0.f, 0.f, 0.f, 0.f);
        float4 u = up4[f];
        int base = r * ST + f * 4;
        s_ih[base + 0] = f2tf(v.x); s_ih[base + 1] = f2tf(v.y);
        s_ih[base + 2] = f2tf(v.z); s_ih[base + 3] = f2tf(v.w);
        s_hu[base + 0] = f2tf(v.x * u.x); s_hu[base + 1] = f2tf(v.y * u.y);
        s_hu[base + 2] = f2tf(v.z * u.z); s_hu[base + 3] = f2tf(v.w * u.w);
    }
    if (tid < 224) s_mask[tid] = (tid < 200) ? mask[b * 200 + tid] : 0.f;
    __syncthreads();

    int wid = tid >> 5, lane = tid & 31, g = lane >> 2, q = lane & 3;
    float* outb = out_adj + (size_t)b * 40000;

    for (int t = wid; t < 49; t += 16) {
        int R = (t / 7) * 32, C = (t % 7) * 32;
        float c[2][4][4];
        #pragma unroll
        for (int mf = 0; mf < 2; mf++)
            #pragma unroll
            for (int nf = 0; nf < 4; nf++)
                #pragma unroll
                for (int x = 0; x < 4; x++) c[mf][nf][x] = 0.f;

        #pragma unroll
        for (int k0 = 0; k0 < 64; k0 += 8) {
            uint32_t A[2][4];
            #pragma unroll
            for (int mf = 0; mf < 2; mf++) {
                const uint32_t* p = s_hu + (R + mf * 16 + g) * ST + k0 + q;
                A[mf][0] = p[0];
                A[mf][1] = p[8 * ST];
                A[mf][2] = p[4];
                A[mf][3] = p[8 * ST + 4];
            }
            #pragma unroll
            for (int nf = 0; nf < 4; nf++) {
                const uint32_t* p = s_ih + (C + nf * 8 + g) * ST + k0 + q;
                uint32_t b0 = p[0], b1 = p[4];
                mma_tf32(c[0][nf], A[0], b0, b1);
                mma_tf32(c[1][nf], A[1], b0, b1);
            }
        }

        #pragma unroll
        for (int mf = 0; mf < 2; mf++)
            #pragma unroll
            for (int sub = 0; sub < 2; sub++) {
                int i = R + mf * 16 + g + sub * 8;
                if (i < 200) {
                    float mi = s_mask[i];
                    #pragma unroll
                    for (int nf = 0; nf < 4; nf++) {
                        int j = C + nf * 8 + 2 * q;
                        if (j < 200) {
                            float v0 = mi * s_mask[j]     / (1.f + __expf(-c[mf][nf][sub * 2 + 0]));
                            float v1 = mi * s_mask[j + 1] / (1.f + __expf(-c[mf][nf][sub * 2 + 1]));
                            *(float2*)(outb + i * 200 + j) = make_float2(v0, v1);
                        }
                    }
                }
            }
    }
}

// ================= hat: hat[b][e] = ih[b,s,:] . W[s,e,:] ======================
// grid (bt=8, s=200), 512 thr. Pre-converted tf32 smem. 4x8=32 warp tiles.
#define HAT_SMEM ((128 * ST + 256 * ST) * 4)
__global__ void __launch_bounds__(512) k_hat(const float* __restrict__ wcap) {
    extern __shared__ uint32_t smu[];
    uint32_t* s_a = smu;               // ih [128][ST] tf32
    uint32_t* s_w = smu + 128 * ST;    // W  [256][ST] tf32
    int bt = blockIdx.x, s = blockIdx.y;
    int tid = threadIdx.x;

    const float4* ih4 = (const float4*)g_ih;
    for (int idx = tid; idx < 128 * 16; idx += 512) {
        int r = idx >> 4, f = idx & 15;
        float4 v = ih4[((size_t)(bt * 128 + r) * 200 + s) * 16 + f];
        int base = r * ST + f * 4;
        s_a[base + 0] = f2tf(v.x); s_a[base + 1] = f2tf(v.y);
        s_a[base + 2] = f2tf(v.z); s_a[base + 3] = f2tf(v.w);
    }
    const float4* w4 = ((const float4*)wcap) + (size_t)s * EE * 16;
    for (int idx = tid; idx < 256 * 16; idx += 512) {
        int r = idx >> 4, f = idx & 15;
        float4 v = w4[idx];
        int base = r * ST + f * 4;
        s_w[base + 0] = f2tf(v.x); s_w[base + 1] = f2tf(v.y);
        s_w[base + 2] = f2tf(v.z); s_w[base + 3] = f2tf(v.w);
    }
    __syncthreads();

    int wid = tid >> 5, lane = tid & 31, g = lane >> 2, q = lane & 3;

    for (int t = wid; t < 32; t += 16) {
        int R = (t & 3) * 32;       // b-local base
        int C = (t >> 2) * 32;      // e base
        float c[2][4][4];
        #pragma unroll
        for (int mf = 0; mf < 2; mf++)
            #pragma unroll
            for (int nf = 0; nf < 4; nf++)
                #pragma unroll
                for (int x = 0; x < 4; x++) c[mf][nf][x] = 0.f;

        #pragma unroll
        for (int k0 = 0; k0 < 64; k0 += 8) {
            uint32_t A[2][4];
            #pragma unroll
            for (int mf = 0; mf < 2; mf++) {
                const uint32_t* p = s_a + (R + mf * 16 + g) * ST + k0 + q;
                A[mf][0] = p[0];
                A[mf][1] = p[8 * ST];
                A[mf][2] = p[4];
                A[mf][3] = p[8 * ST + 4];
            }
            #pragma unroll
            for (int nf = 0; nf < 4; nf++) {
                const uint32_t* p = s_w + (C + nf * 8 + g) * ST + k0 + q;
                uint32_t b0 = p[0], b1 = p[4];
                mma_tf32(c[0][nf], A[0], b0, b1);
                mma_tf32(c[1][nf], A[1], b0, b1);
            }
        }

        #pragma unroll
        for (int mf = 0; mf < 2; mf++)
            #pragma unroll
            for (int sub = 0; sub < 2; sub++) {
                int b_g = bt * 128 + R + mf * 16 + g + sub * 8;
                #pragma unroll
                for (int nf = 0; nf < 4; nf++) {
                    int e = C + nf * 8 + 2 * q;
                    int kk = e >> 6, dd = e & 63;
                    float2 v = make_float2(c[mf][nf][sub * 2 + 0], c[mf][nf][sub * 2 + 1]);
                    *(float2*)(g_hat + (((size_t)b_g * 4 + kk) * 200 + s) * 64 + dd) = v;
                }
            }
    }
}

// ================= routing: 512 threads, split cap-sum ========================
#define ROUT_SMEM ((51200 + 800 + 800 + 256 + 256 + 224 + 512) * 4)
__global__ void __launch_bounds__(512) k_route(const float* __restrict__ mask,
                                               float* __restrict__ out_cap) {
    extern __shared__ float sm[];
    float* s_hat  = sm;               // [4][200][64]
    float* s_cw   = sm + 51200;       // [4][200]
    float* s_sw   = s_cw + 800;       // [4][200]
    float* s_cap  = s_sw + 800;       // [4][64]
    float* s_cq   = s_cap + 256;      // [4][64]
    float* s_mask = s_cq + 256;       // [224]
    float* s_red  = s_mask + 224;     // [512]
    int b = blockIdx.x, tid = threadIdx.x;

    const float4* h4 = (const float4*)(g_hat + (size_t)b * 51200);
    float4* sh4 = (float4*)s_hat;
    for (int i = tid; i < 12800; i += 512) sh4[i] = h4[i];
    for (int i = tid; i < 800; i += 512) s_cw[i] = 0.f;
    if (tid < 200) s_mask[tid] = mask[b * 200 + tid];
    __syncthreads();

    int kd = tid & 255, half = tid >> 8;
    int k = kd >> 6, d = kd & 63;
    int lane = tid & 31, w = tid >> 5;

    for (int it = 0; it < 3; it++) {
        if (tid < 200) {
            float c0 = s_cw[tid],       c1 = s_cw[200 + tid];
            float c2 = s_cw[400 + tid], c3 = s_cw[600 + tid];
            float m = fmaxf(fmaxf(c0, c1), fmaxf(c2, c3));
            float e0 = __expf(c0 - m), e1 = __expf(c1 - m);
            float e2 = __expf(c2 - m), e3 = __expf(c3 - m);
            float inv = 1.f / (e0 + e1 + e2 + e3);
            float mk = s_mask[tid];
            if (mk == 0.f) {
                s_sw[tid] = 0.f; s_sw[200 + tid] = 0.f;
                s_sw[400 + tid] = 0.f; s_sw[600 + tid] = 0.f;
            } else {
                s_sw[tid] = e0 * inv; s_sw[200 + tid] = e1 * inv;
                s_sw[400 + tid] = e2 * inv; s_sw[600 + tid] = e3 * inv;
            }
        }
        __syncthreads();

        // cap[k][d] = sum_s sw[k][s] * hat[k][s][d] — split over 2 halves of s
        float acc = 0.f;
        {
            const float* hk  = s_hat + (k * 200 + half * 100) * 64 + d;
            const float* swk = s_sw + k * 200 + half * 100;
            #pragma unroll 4
            for (int s = 0; s < 100; s++) acc += swk[s] * hk[s * 64];
        }
        s_red[tid] = acc;
        __syncthreads();

        float cq = 0.f;
        if (half == 0) {
            float capv = s_red[tid] + s_red[tid + 256];
            s_cap[kd] = capv;
        }
        __syncthreads();
        if (half == 0) {
            float n = 0.f;
            const float* ck = s_cap + k * 64;
            #pragma unroll 8
            for (int dd = 0; dd < 64; dd++) { float v = ck[dd]; n += v * v; }
            float scale = n / (1.f + n) * rsqrtf(n + 1e-9f);
            cq = s_cap[kd] * scale;
            if (it == 2) out_cap[b * 256 + kd] = cq;
            else         s_cq[kd] = cq;
        }

        if (it < 2) {
            __syncthreads();
            // delta[k][s] = dot(hat[k][s][:], cq[k][:]);  cw += delta — 16 warps
            for (int p = w; p < 800; p += 16) {
                int kk = p / 200, ss = p % 200;
                const float* hr = s_hat + (kk * 200 + ss) * 64;
                float v = hr[lane] * s_cq[kk * 64 + lane] +
                          hr[32 + lane] * s_cq[kk * 64 + 32 + lane];
                v += __shfl_xor_sync(0xffffffffu, v, 16);
                v += __shfl_xor_sync(0xffffffffu, v, 8);
                v += __shfl_xor_sync(0xffffffffu, v, 4);
                v += __shfl_xor_sync(0xffffffffu, v, 2);
                v += __shfl_xor_sync(0xffffffffu, v, 1);
                if (lane == 0) s_cw[kk * 200 + ss] += v;
            }
            __syncthreads();
        }
    }
}

// ================= launcher ===================================================
extern "C" void kernel_launch(void* const* d_in, const int* in_sizes, int n_in,
                              void* d_out, int out_size) {
    const int*   uid    = (const int*)d_in[0];
    const int*   age    = (const int*)d_in[1];
    const int*   gender = (const int*)d_in[2];
    const int*   occup  = (const int*)d_in[3];
    const int*   mid    = (const int*)d_in[4];
    const float* mask   = (const float*)d_in[5];
    const float* ut     = (const float*)d_in[6];
    const float* at     = (const float*)d_in[7];
    const float* gt     = (const float*)d_in[8];
    const float* ot     = (const float*)d_in[9];
    const float* memb   = (const float*)d_in[10];
    const float* wcap   = (const float*)d_in[11];

    float* out_cap = (float*)d_out;
    float* out_adj = (float*)d_out + BB * NI * DD;

    cudaFuncSetAttribute(k_adj,   cudaFuncAttributeMaxDynamicSharedMemorySize, ADJ_SMEM);
    cudaFuncSetAttribute(k_hat,   cudaFuncAttributeMaxDynamicSharedMemorySize, HAT_SMEM);
    cudaFuncSetAttribute(k_route, cudaFuncAttributeMaxDynamicSharedMemorySize, ROUT_SMEM);

    k_prep_up<<<(BB * DD + 255) / 256, 256>>>(uid, age, gender, occup, ut, at, gt, ot);
    k_prep_ih<<<(BB * SS * 16 + 255) / 256, 256>>>(mid, mask, memb);
    k_hat<<<dim3(8, SS), 512, HAT_SMEM>>>(wcap);
    k_adj<<<BB, 512, ADJ_SMEM>>>(mask, out_adj);
    k_route<<<BB, 512, ROUT_SMEM>>>(mask, out_cap);
}

// round 12
// speedup vs baseline: 1.9954x; 1.2823x over previous
#include <cuda_runtime.h>
#include <cstdint>

#define BB 1024
#define SS 200
#define DD 64
#define NI 4
#define EE 256   // NI*DD

// ================= mma.sync tf32 helpers =====================================
__device__ __forceinline__ uint32_t f2tf(float f) {
    uint32_t r; asm("cvt.rna.tf32.f32 %0, %1;" : "=r"(r) : "f"(f)); return r;
}
__device__ __forceinline__ void mma_tf32(float* c, const uint32_t* a, uint32_t b0, uint32_t b1) {
    asm volatile("mma.sync.aligned.m16n8k8.row.col.f32.tf32.tf32.f32 "
        "{%0,%1,%2,%3}, {%4,%5,%6,%7}, {%8,%9}, {%0,%1,%2,%3};"
        : "+f"(c[0]), "+f"(c[1]), "+f"(c[2]), "+f"(c[3])
        : "r"(a[0]), "r"(a[1]), "r"(a[2]), "r"(a[3]), "r"(b0), "r"(b1));
}

// Fragment-ordered smem. A: per (mb=16-row block, lane, chunk) a uint4
// {A[16mb+g, 8c+q], A[16mb+8+g, 8c+q], A[16mb+g, 8c+4+q], A[16mb+8+g, 8c+4+q]},
// g=lane>>2, q=lane&3. Chunk dim padded 8->9 (uint4 lane-stride 144B: conflict-free).
// B: per (nb=8-row block, lane, chunk) a uint2 {B[8nb+g, 8c+q], B[8nb+g, 8c+4+q]}.
// value (r,k): lane=(r&7)*4+(k&3); A slot=((r>>3)&1)+2*((k>>2)&1); B slot=(k>>2)&1.

// ================= scratch ====================================================
__device__ float g_up[BB * DD];
__device__ float g_ih[BB * SS * DD];
__device__ float g_hat[BB * NI * SS * DD];   // fp32 — bf16 broke output-0 rel_err

// ================= prep =======================================================
__global__ void k_prep_up(const int* __restrict__ uid, const int* __restrict__ age,
                          const int* __restrict__ gender, const int* __restrict__ occup,
                          const float* __restrict__ ut, const float* __restrict__ at,
                          const float* __restrict__ gt, const float* __restrict__ ot) {
    int idx = blockIdx.x * blockDim.x + threadIdx.x;
    if (idx >= BB * DD) return;
    int b = idx >> 6, d = idx & 63;
    g_up[idx] = 0.25f * (ut[uid[b] * 64 + d] + gt[gender[b] * 64 + d] +
                         at[age[b] * 64 + d] + ot[occup[b] * 64 + d]);
}

__global__ void k_prep_ih(const int* __restrict__ mid, const float* __restrict__ mask,
                          const float* __restrict__ memb) {
    int idx = blockIdx.x * blockDim.x + threadIdx.x;
    if (idx >= BB * SS * 16) return;
    int bs = idx >> 4, f = idx & 15;
    float m = mask[bs];
    int row = mid[bs];
    float4 v = ((const float4*)memb)[row * 16 + f];
    float4 o; o.x = v.x * m; o.y = v.y * m; o.z = v.z * m; o.w = v.w * m;
    ((float4*)g_ih)[idx] = o;
}

// ================= adj ========================================================
// grid (ihalf=2, b=1024), 512 thr. CTA covers i rows [ihalf*128, +128/96).
// A(hu) frag: up to 8 mb; B(ih) frag: 28 nb (full 224 j rows, zero-padded).
#define ADJ_A_WORDS (8 * 32 * 9 * 4)    // 9216
#define ADJ_B_WORDS (28 * 32 * 9 * 2)   // 16128
#define ADJ_SMEM ((ADJ_A_WORDS + ADJ_B_WORDS + 224) * 4)
__global__ void __launch_bounds__(512) k_adj(const float* __restrict__ mask,
                                             float* __restrict__ out_adj) {
    extern __shared__ uint32_t smu[];
    uint32_t* s_a = smu;                                   // A fragments
    uint32_t* s_b = smu + ADJ_A_WORDS;                     // B fragments
    float*    s_mask = (float*)(smu + ADJ_A_WORDS + ADJ_B_WORDS);
    int ihalf = blockIdx.x, b = blockIdx.y;
    int tid = threadIdx.x;
    int nrows = ihalf ? 96 : 128;

    const float4* ih4 = ((const float4*)g_ih) + (size_t)b * 200 * 16;
    const float4* up4 = ((const float4*)g_up) + b * 16;
    for (int idx = tid; idx < 224 * 16; idx += 512) {
        int r = idx >> 4, f = idx & 15;
        float4 v = (r < 200) ? ih4[r * 16 + f] : make_float4(0.f, 0.f, 0.f, 0.f);
        int c = f >> 1, kh = f & 1;
        // B frag (ih), all 224 rows
        int bw = (((r >> 3) * 32 + (r & 7) * 4) * 9 + c) * 2 + kh;
        s_b[bw +  0] = f2tf(v.x); s_b[bw + 18] = f2tf(v.y);
        s_b[bw + 36] = f2tf(v.z); s_b[bw + 54] = f2tf(v.w);
        // A frag (hu), this CTA's rows only
        int rl = r - ihalf * 128;
        if (rl >= 0 && rl < nrows) {
            float4 u = up4[f];
            int aw = (((rl >> 4) * 32 + (rl & 7) * 4) * 9 + c) * 4
                   + ((rl >> 3) & 1) + 2 * kh;
            s_a[aw +   0] = f2tf(v.x * u.x); s_a[aw +  36] = f2tf(v.y * u.y);
            s_a[aw +  72] = f2tf(v.z * u.z); s_a[aw + 108] = f2tf(v.w * u.w);
        }
    }
    if (tid < 224) s_mask[tid] = (tid < 200) ? mask[b * 200 + tid] : 0.f;
    __syncthreads();

    int wid = tid >> 5, lane = tid & 31, g = lane >> 2, q = lane & 3;
    float* outb = out_adj + (size_t)b * 40000;
    const uint4* pa = (const uint4*)s_a;
    const uint2* pb = (const uint2*)s_b;
    int ntiles = (ihalf ? 3 : 4) * 7;

    for (int t = wid; t < ntiles; t += 16) {
        int mb0 = (t / 7) * 2;          // local mb base
        int nb0 = (t % 7) * 4;
        float c[2][4][4];
        #pragma unroll
        for (int mf = 0; mf < 2; mf++)
            #pragma unroll
            for (int nf = 0; nf < 4; nf++)
                #pragma unroll
                for (int x = 0; x < 4; x++) c[mf][nf][x] = 0.f;

        #pragma unroll
        for (int cc = 0; cc < 8; cc++) {
            uint4 A0 = pa[(mb0 * 32 + lane) * 9 + cc];
            uint4 A1 = pa[((mb0 + 1) * 32 + lane) * 9 + cc];
            #pragma unroll
            for (int nf = 0; nf < 4; nf++) {
                uint2 B = pb[((nb0 + nf) * 32 + lane) * 9 + cc];
                mma_tf32(c[0][nf], (const uint32_t*)&A0, B.x, B.y);
                mma_tf32(c[1][nf], (const uint32_t*)&A1, B.x, B.y);
            }
        }

        #pragma unroll
        for (int mf = 0; mf < 2; mf++)
            #pragma unroll
            for (int sub = 0; sub < 2; sub++) {
                int i = ihalf * 128 + (mb0 + mf) * 16 + g + sub * 8;
                if (i < 200) {
                    float mi = s_mask[i];
                    #pragma unroll
                    for (int nf = 0; nf < 4; nf++) {
                        int j = (nb0 + nf) * 8 + 2 * q;
                        if (j < 200) {
                            float v0 = __fdividef(mi * s_mask[j],
                                        1.f + __expf(-c[mf][nf][sub * 2 + 0]));
                            float v1 = __fdividef(mi * s_mask[j + 1],
                                        1.f + __expf(-c[mf][nf][sub * 2 + 1]));
                            *(float2*)(outb + i * 200 + j) = make_float2(v0, v1);
                        }
                    }
                }
            }
    }
}

// ================= hat ========================================================
// grid (bt=4, s=200), 512 thr. A = ih rows [bt*256,+256) (16 mb), B = W[s] (32 nb).
// D[b][e]; output float2 to g_hat (B,K,S,D).
#define HAT_A_WORDS (16 * 32 * 9 * 4)   // 18432
#define HAT_B_WORDS (32 * 32 * 9 * 2)   // 18432
#define HAT_SMEM ((HAT_A_WORDS + HAT_B_WORDS) * 4)
__global__ void __launch_bounds__(512) k_hat(const float* __restrict__ wcap) {
    extern __shared__ uint32_t smu[];
    uint32_t* s_a = smu;
    uint32_t* s_b = smu + HAT_A_WORDS;
    int bt = blockIdx.x, s = blockIdx.y;
    int tid = threadIdx.x;

    const float4* ih4 = (const float4*)g_ih;
    for (int idx = tid; idx < 256 * 16; idx += 512) {
        int r = idx >> 4, f = idx & 15;
        float4 v = ih4[((size_t)(bt * 256 + r) * 200 + s) * 16 + f];
        int c = f >> 1, kh = f & 1;
        int aw = (((r >> 4) * 32 + (r & 7) * 4) * 9 + c) * 4 + ((r >> 3) & 1) + 2 * kh;
        s_a[aw +   0] = f2tf(v.x); s_a[aw +  36] = f2tf(v.y);
        s_a[aw +  72] = f2tf(v.z); s_a[aw + 108] = f2tf(v.w);
    }
    const float4* w4 = ((const float4*)wcap) + (size_t)s * EE * 16;
    for (int idx = tid; idx < 256 * 16; idx += 512) {
        int e = idx >> 4, f = idx & 15;
        float4 v = w4[idx];
        int c = f >> 1, kh = f & 1;
        int bw = (((e >> 3) * 32 + (e & 7) * 4) * 9 + c) * 2 + kh;
        s_b[bw +  0] = f2tf(v.x); s_b[bw + 18] = f2tf(v.y);
        s_b[bw + 36] = f2tf(v.z); s_b[bw + 54] = f2tf(v.w);
    }
    __syncthreads();

    int wid = tid >> 5, lane = tid & 31, g = lane >> 2, q = lane & 3;
    const uint4* pa = (const uint4*)s_a;
    const uint2* pb = (const uint2*)s_b;

    for (int t = wid; t < 64; t += 16) {
        int mb0 = (t >> 3) * 2;       // b tile
        int nb0 = (t & 7) * 4;        // e tile
        float c[2][4][4];
        #pragma unroll
        for (int mf = 0; mf < 2; mf++)
            #pragma unroll
            for (int nf = 0; nf < 4; nf++)
                #pragma unroll
                for (int x = 0; x < 4; x++) c[mf][nf][x] = 0.f;

        #pragma unroll
        for (int cc = 0; cc < 8; cc++) {
            uint4 A0 = pa[(mb0 * 32 + lane) * 9 + cc];
            uint4 A1 = pa[((mb0 + 1) * 32 + lane) * 9 + cc];
            #pragma unroll
            for (int nf = 0; nf < 4; nf++) {
                uint2 B = pb[((nb0 + nf) * 32 + lane) * 9 + cc];
                mma_tf32(c[0][nf], (const uint32_t*)&A0, B.x, B.y);
                mma_tf32(c[1][nf], (const uint32_t*)&A1, B.x, B.y);
            }
        }

        #pragma unroll
        for (int mf = 0; mf < 2; mf++)
            #pragma unroll
            for (int sub = 0; sub < 2; sub++) {
                int b_g = bt * 256 + (mb0 + mf) * 16 + g + sub * 8;
                #pragma unroll
                for (int nf = 0; nf < 4; nf++) {
                    int e = (nb0 + nf) * 8 + 2 * q;
                    int kk = e >> 6, dd = e & 63;
                    float2 v = make_float2(c[mf][nf][sub * 2 + 0], c[mf][nf][sub * 2 + 1]);
                    *(float2*)(g_hat + (((size_t)b_g * 4 + kk) * 200 + s) * 64 + dd) = v;
                }
            }
    }
}

// ================= routing: 512 threads =======================================
#define ROUT_SMEM ((51200 + 800 + 800 + 256 + 256 + 224 + 512) * 4)
__global__ void __launch_bounds__(512) k_route(const float* __restrict__ mask,
                                               float* __restrict__ out_cap) {
    extern __shared__ float sm[];
    float* s_hat  = sm;               // [4][200][64] fp32
    float* s_cw   = sm + 51200;
    float* s_sw   = s_cw + 800;
    float* s_cap  = s_sw + 800;
    float* s_cq   = s_cap + 256;
    float* s_mask = s_cq + 256;
    float* s_red  = s_mask + 224;
    int b = blockIdx.x, tid = threadIdx.x;

    const float4* h4 = (const float4*)(g_hat + (size_t)b * 51200);
    float4* sh4 = (float4*)s_hat;
    for (int i = tid; i < 12800; i += 512) sh4[i] = h4[i];
    for (int i = tid; i < 800; i += 512) s_cw[i] = 0.f;
    if (tid < 200) s_mask[tid] = mask[b * 200 + tid];
    __syncthreads();

    int kd = tid & 255, half = tid >> 8;
    int k = kd >> 6, d = kd & 63;
    int lane = tid & 31, w = tid >> 5;

    for (int it = 0; it < 3; it++) {
        if (tid < 200) {
            float c0 = s_cw[tid],       c1 = s_cw[200 + tid];
            float c2 = s_cw[400 + tid], c3 = s_cw[600 + tid];
            float m = fmaxf(fmaxf(c0, c1), fmaxf(c2, c3));
            float e0 = __expf(c0 - m), e1 = __expf(c1 - m);
            float e2 = __expf(c2 - m), e3 = __expf(c3 - m);
            float inv = __fdividef(1.f, e0 + e1 + e2 + e3);
            float mk = s_mask[tid];
            if (mk == 0.f) {
                s_sw[tid] = 0.f; s_sw[200 + tid] = 0.f;
                s_sw[400 + tid] = 0.f; s_sw[600 + tid] = 0.f;
            } else {
                s_sw[tid] = e0 * inv; s_sw[200 + tid] = e1 * inv;
                s_sw[400 + tid] = e2 * inv; s_sw[600 + tid] = e3 * inv;
            }
        }
        __syncthreads();

        float acc = 0.f;
        {
            const float* hk  = s_hat + (k * 200 + half * 100) * 64 + d;
            const float* swk = s_sw + k * 200 + half * 100;
            #pragma unroll 4
            for (int s = 0; s < 100; s++) acc += swk[s] * hk[s * 64];
        }
        s_red[tid] = acc;
        __syncthreads();

        if (half == 0) s_cap[kd] = s_red[tid] + s_red[tid + 256];
        __syncthreads();
        if (half == 0) {
            float n = 0.f;
            const float* ck = s_cap + k * 64;
            #pragma unroll 8
            for (int dd = 0; dd < 64; dd++) { float v = ck[dd]; n += v * v; }
            float scale = n / (1.f + n) * rsqrtf(n + 1e-9f);
            float cq = s_cap[kd] * scale;
            if (it == 2) out_cap[b * 256 + kd] = cq;
            else         s_cq[kd] = cq;
        }

        if (it < 2) {
            __syncthreads();
            for (int p = w; p < 800; p += 16) {
                int kk = p / 200, ss = p % 200;
                const float* hr = s_hat + (kk * 200 + ss) * 64;
                float v = hr[lane] * s_cq[kk * 64 + lane] +
                          hr[32 + lane] * s_cq[kk * 64 + 32 + lane];
                v += __shfl_xor_sync(0xffffffffu, v, 16);
                v += __shfl_xor_sync(0xffffffffu, v, 8);
                v += __shfl_xor_sync(0xffffffffu, v, 4);
                v += __shfl_xor_sync(0xffffffffu, v, 2);
                v += __shfl_xor_sync(0xffffffffu, v, 1);
                if (lane == 0) s_cw[kk * 200 + ss] += v;
            }
            __syncthreads();
        }
    }
}

// ================= launcher ===================================================
extern "C" void kernel_launch(void* const* d_in, const int* in_sizes, int n_in,
                              void* d_out, int out_size) {
    const int*   uid    = (const int*)d_in[0];
    const int*   age    = (const int*)d_in[1];
    const int*   gender = (const int*)d_in[2];
    const int*   occup  = (const int*)d_in[3];
    const int*   mid    = (const int*)d_in[4];
    const float* mask   = (const float*)d_in[5];
    const float* ut     = (const float*)d_in[6];
    const float* at     = (const float*)d_in[7];
    const float* gt     = (const float*)d_in[8];
    const float* ot     = (const float*)d_in[9];
    const float* memb   = (const float*)d_in[10];
    const float* wcap   = (const float*)d_in[11];

    float* out_cap = (float*)d_out;
    float* out_adj = (float*)d_out + BB * NI * DD;

    cudaFuncSetAttribute(k_adj,   cudaFuncAttributeMaxDynamicSharedMemorySize, ADJ_SMEM);
    cudaFuncSetAttribute(k_hat,   cudaFuncAttributeMaxDynamicSharedMemorySize, HAT_SMEM);
    cudaFuncSetAttribute(k_route, cudaFuncAttributeMaxDynamicSharedMemorySize, ROUT_SMEM);

    k_prep_up<<<(BB * DD + 255) / 256, 256>>>(uid, age, gender, occup, ut, at, gt, ot);
    k_prep_ih<<<(BB * SS * 16 + 255) / 256, 256>>>(mid, mask, memb);
    k_hat<<<dim3(4, SS), 512, HAT_SMEM>>>(wcap);
    k_adj<<<dim3(2, BB), 512, ADJ_SMEM>>>(mask, out_adj);
    k_route<<<BB, 512, ROUT_SMEM>>>(mask, out_cap);
}

// round 14
// speedup vs baseline: 2.0765x; 1.0407x over previous
#include <cuda_runtime.h>
#include <cuda_fp16.h>
#include <cstdint>

#define BB 1024
#define SS 200
#define DD 64
#define NI 4
#define EE 256   // NI*DD

// ================= mma.sync tf32 helpers =====================================
__device__ __forceinline__ uint32_t f2tf(float f) {
    uint32_t r; asm("cvt.rna.tf32.f32 %0, %1;" : "=r"(r) : "f"(f)); return r;
}
__device__ __forceinline__ void mma_tf32(float* c, const uint32_t* a, uint32_t b0, uint32_t b1) {
    asm volatile("mma.sync.aligned.m16n8k8.row.col.f32.tf32.tf32.f32 "
        "{%0,%1,%2,%3}, {%4,%5,%6,%7}, {%8,%9}, {%0,%1,%2,%3};"
        : "+f"(c[0]), "+f"(c[1]), "+f"(c[2]), "+f"(c[3])
        : "r"(a[0]), "r"(a[1]), "r"(a[2]), "r"(a[3]), "r"(b0), "r"(b1));
}

// Fragment-ordered smem (see R12): A uint4 per (mb,lane,chunk), chunk padded to 9;
// B uint2 per (nb,lane,chunk).

// ================= scratch ====================================================
__device__ float g_up[BB * DD];
__device__ float g_ih[BB * SS * DD];
__device__ __half g_hat[BB * NI * SS * DD];   // fp16: 105MB (bf16 too coarse, fp32 too slow)

// ================= prep =======================================================
__global__ void k_prep_up(const int* __restrict__ uid, const int* __restrict__ age,
                          const int* __restrict__ gender, const int* __restrict__ occup,
                          const float* __restrict__ ut, const float* __restrict__ at,
                          const float* __restrict__ gt, const float* __restrict__ ot) {
    int idx = blockIdx.x * blockDim.x + threadIdx.x;
    if (idx >= BB * DD) return;
    int b = idx >> 6, d = idx & 63;
    g_up[idx] = 0.25f * (ut[uid[b] * 64 + d] + gt[gender[b] * 64 + d] +
                         at[age[b] * 64 + d] + ot[occup[b] * 64 + d]);
}

__global__ void k_prep_ih(const int* __restrict__ mid, const float* __restrict__ mask,
                          const float* __restrict__ memb) {
    int idx = blockIdx.x * blockDim.x + threadIdx.x;
    if (idx >= BB * SS * 16) return;
    int bs = idx >> 4, f = idx & 15;
    float m = mask[bs];
    int row = mid[bs];
    float4 v = ((const float4*)memb)[row * 16 + f];
    float4 o; o.x = v.x * m; o.y = v.y * m; o.z = v.z * m; o.w = v.w * m;
    ((float4*)g_ih)[idx] = o;
}

// ================= adj (unchanged from R12 — 87.4us measured) =================
#define ADJ_A_WORDS (8 * 32 * 9 * 4)    // 9216
#define ADJ_B_WORDS (28 * 32 * 9 * 2)   // 16128
#define ADJ_SMEM ((ADJ_A_WORDS + ADJ_B_WORDS + 224) * 4)
__global__ void __launch_bounds__(512) k_adj(const float* __restrict__ mask,
                                             float* __restrict__ out_adj) {
    extern __shared__ uint32_t smu[];
    uint32_t* s_a = smu;
    uint32_t* s_b = smu + ADJ_A_WORDS;
    float*    s_mask = (float*)(smu + ADJ_A_WORDS + ADJ_B_WORDS);
    int ihalf = blockIdx.x, b = blockIdx.y;
    int tid = threadIdx.x;
    int nrows = ihalf ? 96 : 128;

    const float4* ih4 = ((const float4*)g_ih) + (size_t)b * 200 * 16;
    const float4* up4 = ((const float4*)g_up) + b * 16;
    for (int idx = tid; idx < 224 * 16; idx += 512) {
        int r = idx >> 4, f = idx & 15;
        float4 v = (r < 200) ? ih4[r * 16 + f] : make_float4(0.f, 0.f, 0.f, 0.f);
        int c = f >> 1, kh = f & 1;
        int bw = (((r >> 3) * 32 + (r & 7) * 4) * 9 + c) * 2 + kh;
        s_b[bw +  0] = f2tf(v.x); s_b[bw + 18] = f2tf(v.y);
        s_b[bw + 36] = f2tf(v.z); s_b[bw + 54] = f2tf(v.w);
        int rl = r - ihalf * 128;
        if (rl >= 0 && rl < nrows) {
            float4 u = up4[f];
            int aw = (((rl >> 4) * 32 + (rl & 7) * 4) * 9 + c) * 4
                   + ((rl >> 3) & 1) + 2 * kh;
            s_a[aw +   0] = f2tf(v.x * u.x); s_a[aw +  36] = f2tf(v.y * u.y);
            s_a[aw +  72] = f2tf(v.z * u.z); s_a[aw + 108] = f2tf(v.w * u.w);
        }
    }
    if (tid < 224) s_mask[tid] = (tid < 200) ? mask[b * 200 + tid] : 0.f;
    __syncthreads();

    int wid = tid >> 5, lane = tid & 31, g = lane >> 2, q = lane & 3;
    float* outb = out_adj + (size_t)b * 40000;
    const uint4* pa = (const uint4*)s_a;
    const uint2* pb = (const uint2*)s_b;
    int ntiles = (ihalf ? 3 : 4) * 7;

    for (int t = wid; t < ntiles; t += 16) {
        int mb0 = (t / 7) * 2;
        int nb0 = (t % 7) * 4;
        float c[2][4][4];
        #pragma unroll
        for (int mf = 0; mf < 2; mf++)
            #pragma unroll
            for (int nf = 0; nf < 4; nf++)
                #pragma unroll
                for (int x = 0; x < 4; x++) c[mf][nf][x] = 0.f;

        #pragma unroll
        for (int cc = 0; cc < 8; cc++) {
            uint4 A0 = pa[(mb0 * 32 + lane) * 9 + cc];
            uint4 A1 = pa[((mb0 + 1) * 32 + lane) * 9 + cc];
            #pragma unroll
            for (int nf = 0; nf < 4; nf++) {
                uint2 B = pb[((nb0 + nf) * 32 + lane) * 9 + cc];
                mma_tf32(c[0][nf], (const uint32_t*)&A0, B.x, B.y);
                mma_tf32(c[1][nf], (const uint32_t*)&A1, B.x, B.y);
            }
        }

        #pragma unroll
        for (int mf = 0; mf < 2; mf++)
            #pragma unroll
            for (int sub = 0; sub < 2; sub++) {
                int i = ihalf * 128 + (mb0 + mf) * 16 + g + sub * 8;
                if (i < 200) {
                    float mi = s_mask[i];
                    #pragma unroll
                    for (int nf = 0; nf < 4; nf++) {
                        int j = (nb0 + nf) * 8 + 2 * q;
                        if (j < 200) {
                            float v0 = __fdividef(mi * s_mask[j],
                                        1.f + __expf(-c[mf][nf][sub * 2 + 0]));
                            float v1 = __fdividef(mi * s_mask[j + 1],
                                        1.f + __expf(-c[mf][nf][sub * 2 + 1]));
                            *(float2*)(outb + i * 200 + j) = make_float2(v0, v1);
                        }
                    }
                }
            }
    }
}

// ================= hat ========================================================
// grid (bt=8, s=200), 512 thr. A = ih rows [bt*128,+128) (8 mb), B = W[s] (32 nb).
// smem 110.6KB -> 2 CTAs/SM. Output __half2 to g_hat (B,K,S,D).
#define HAT_A_WORDS (8 * 32 * 9 * 4)    // 9216
#define HAT_B_WORDS (32 * 32 * 9 * 2)   // 18432
#define HAT_SMEM ((HAT_A_WORDS + HAT_B_WORDS) * 4)
__global__ void __launch_bounds__(512) k_hat(const float* __restrict__ wcap) {
    extern __shared__ uint32_t smu[];
    uint32_t* s_a = smu;
    uint32_t* s_b = smu + HAT_A_WORDS;
    int bt = blockIdx.x, s = blockIdx.y;
    int tid = threadIdx.x;

    const float4* ih4 = (const float4*)g_ih;
    for (int idx = tid; idx < 128 * 16; idx += 512) {
        int r = idx >> 4, f = idx & 15;
        float4 v = ih4[((size_t)(bt * 128 + r) * 200 + s) * 16 + f];
        int c = f >> 1, kh = f & 1;
        int aw = (((r >> 4) * 32 + (r & 7) * 4) * 9 + c) * 4 + ((r >> 3) & 1) + 2 * kh;
        s_a[aw +   0] = f2tf(v.x); s_a[aw +  36] = f2tf(v.y);
        s_a[aw +  72] = f2tf(v.z); s_a[aw + 108] = f2tf(v.w);
    }
    const float4* w4 = ((const float4*)wcap) + (size_t)s * EE * 16;
    for (int idx = tid; idx < 256 * 16; idx += 512) {
        int e = idx >> 4, f = idx & 15;
        float4 v = w4[idx];
        int c = f >> 1, kh = f & 1;
        int bw = (((e >> 3) * 32 + (e & 7) * 4) * 9 + c) * 2 + kh;
        s_b[bw +  0] = f2tf(v.x); s_b[bw + 18] = f2tf(v.y);
        s_b[bw + 36] = f2tf(v.z); s_b[bw + 54] = f2tf(v.w);
    }
    __syncthreads();

    int wid = tid >> 5, lane = tid & 31, g = lane >> 2, q = lane & 3;
    const uint4* pa = (const uint4*)s_a;
    const uint2* pb = (const uint2*)s_b;

    for (int t = wid; t < 32; t += 16) {
        int mb0 = (t >> 3) * 2;       // b tile (0,2,4,6)
        int nb0 = (t & 7) * 4;        // e tile
        float c[2][4][4];
        #pragma unroll
        for (int mf = 0; mf < 2; mf++)
            #pragma unroll
            for (int nf = 0; nf < 4; nf++)
                #pragma unroll
                for (int x = 0; x < 4; x++) c[mf][nf][x] = 0.f;

        #pragma unroll
        for (int cc = 0; cc < 8; cc++) {
            uint4 A0 = pa[(mb0 * 32 + lane) * 9 + cc];
            uint4 A1 = pa[((mb0 + 1) * 32 + lane) * 9 + cc];
            #pragma unroll
            for (int nf = 0; nf < 4; nf++) {
                uint2 B = pb[((nb0 + nf) * 32 + lane) * 9 + cc];
                mma_tf32(c[0][nf], (const uint32_t*)&A0, B.x, B.y);
                mma_tf32(c[1][nf], (const uint32_t*)&A1, B.x, B.y);
            }
        }

        #pragma unroll
        for (int mf = 0; mf < 2; mf++)
            #pragma unroll
            for (int sub = 0; sub < 2; sub++) {
                int b_g = bt * 128 + (mb0 + mf) * 16 + g + sub * 8;
                #pragma unroll
                for (int nf = 0; nf < 4; nf++) {
                    int e = (nb0 + nf) * 8 + 2 * q;
                    int kk = e >> 6, dd = e & 63;
                    __half2 hv = __float22half2_rn(
                        make_float2(c[mf][nf][sub * 2 + 0], c[mf][nf][sub * 2 + 1]));
                    *(__half2*)(g_hat + (((size_t)b_g * 4 + kk) * 200 + s) * 64 + dd) = hv;
                }
            }
    }
}

// ================= routing: 512 threads, fp16 hat staging =====================
#define ROUT_SMEM ((51200 + 800 + 800 + 256 + 256 + 224 + 512) * 4)
__global__ void __launch_bounds__(512) k_route(const float* __restrict__ mask,
                                               float* __restrict__ out_cap) {
    extern __shared__ float sm[];
    float* s_hat  = sm;               // [4][200][64] fp32
    float* s_cw   = sm + 51200;
    float* s_sw   = s_cw + 800;
    float* s_cap  = s_sw + 800;
    float* s_cq   = s_cap + 256;
    float* s_mask = s_cq + 256;
    float* s_red  = s_mask + 224;
    int b = blockIdx.x, tid = threadIdx.x;

    const uint4* h4 = (const uint4*)(g_hat + (size_t)b * 51200);   // 8 halves per uint4
    float2* sh2 = (float2*)s_hat;
    for (int i = tid; i < 6400; i += 512) {
        uint4 u = h4[i];
        const __half2* hp = (const __half2*)&u;
        sh2[i * 4 + 0] = __half22float2(hp[0]);
        sh2[i * 4 + 1] = __half22float2(hp[1]);
        sh2[i * 4 + 2] = __half22float2(hp[2]);
        sh2[i * 4 + 3] = __half22float2(hp[3]);
    }
    for (int i = tid; i < 800; i += 512) s_cw[i] = 0.f;
    if (tid < 200) s_mask[tid] = mask[b * 200 + tid];
    __syncthreads();

    int kd = tid & 255, half = tid >> 8;
    int k = kd >> 6, d = kd & 63;
    int lane = tid & 31, w = tid >> 5;

    for (int it = 0; it < 3; it++) {
        if (tid < 200) {
            float c0 = s_cw[tid],       c1 = s_cw[200 + tid];
            float c2 = s_cw[400 + tid], c3 = s_cw[600 + tid];
            float m = fmaxf(fmaxf(c0, c1), fmaxf(c2, c3));
            float e0 = __expf(c0 - m), e1 = __expf(c1 - m);
            float e2 = __expf(c2 - m), e3 = __expf(c3 - m);
            float inv = __fdividef(1.f, e0 + e1 + e2 + e3);
            float mk = s_mask[tid];
            if (mk == 0.f) {
                s_sw[tid] = 0.f; s_sw[200 + tid] = 0.f;
                s_sw[400 + tid] = 0.f; s_sw[600 + tid] = 0.f;
            } else {
                s_sw[tid] = e0 * inv; s_sw[200 + tid] = e1 * inv;
                s_sw[400 + tid] = e2 * inv; s_sw[600 + tid] = e3 * inv;
            }
        }
        __syncthreads();

        float acc = 0.f;
        {
            const float* hk  = s_hat + (k * 200 + half * 100) * 64 + d;
            const float* swk = s_sw + k * 200 + half * 100;
            #pragma unroll 4
            for (int s = 0; s < 100; s++) acc += swk[s] * hk[s * 64];
        }
        s_red[tid] = acc;
        __syncthreads();

        if (half == 0) s_cap[kd] = s_red[tid] + s_red[tid + 256];
        __syncthreads();
        if (half == 0) {
            float n = 0.f;
            const float* ck = s_cap + k * 64;
            #pragma unroll 8
            for (int dd = 0; dd < 64; dd++) { float v = ck[dd]; n += v * v; }
            float scale = n / (1.f + n) * rsqrtf(n + 1e-9f);
            float cq = s_cap[kd] * scale;
            if (it == 2) out_cap[b * 256 + kd] = cq;
            else         s_cq[kd] = cq;
        }

        if (it < 2) {
            __syncthreads();
            for (int p = w; p < 800; p += 16) {
                int kk = p / 200, ss = p % 200;
                const float* hr = s_hat + (kk * 200 + ss) * 64;
                float v = hr[lane] * s_cq[kk * 64 + lane] +
                          hr[32 + lane] * s_cq[kk * 64 + 32 + lane];
                v += __shfl_xor_sync(0xffffffffu, v, 16);
                v += __shfl_xor_sync(0xffffffffu, v, 8);
                v += __shfl_xor_sync(0xffffffffu, v, 4);
                v += __shfl_xor_sync(0xffffffffu, v, 2);
                v += __shfl_xor_sync(0xffffffffu, v, 1);
                if (lane == 0) s_cw[kk * 200 + ss] += v;
            }
            __syncthreads();
        }
    }
}

// ================= launcher ===================================================
extern "C" void kernel_launch(void* const* d_in, const int* in_sizes, int n_in,
                              void* d_out, int out_size) {
    const int*   uid    = (const int*)d_in[0];
    const int*   age    = (const int*)d_in[1];
    const int*   gender = (const int*)d_in[2];
    const int*   occup  = (const int*)d_in[3];
    const int*   mid    = (const int*)d_in[4];
    const float* mask   = (const float*)d_in[5];
    const float* ut     = (const float*)d_in[6];
    const float* at     = (const float*)d_in[7];
    const float* gt     = (const float*)d_in[8];
    const float* ot     = (const float*)d_in[9];
    const float* memb   = (const float*)d_in[10];
    const float* wcap   = (const float*)d_in[11];

    float* out_cap = (float*)d_out;
    float* out_adj = (float*)d_out + BB * NI * DD;

    cudaFuncSetAttribute(k_adj,   cudaFuncAttributeMaxDynamicSharedMemorySize, ADJ_SMEM);
    cudaFuncSetAttribute(k_hat,   cudaFuncAttributeMaxDynamicSharedMemorySize, HAT_SMEM);
    cudaFuncSetAttribute(k_route, cudaFuncAttributeMaxDynamicSharedMemorySize, ROUT_SMEM);

    k_prep_up<<<(BB * DD + 255) / 256, 256>>>(uid, age, gender, occup, ut, at, gt, ot);
    k_prep_ih<<<(BB * SS * 16 + 255) / 256, 256>>>(mid, mask, memb);
    k_hat<<<dim3(8, SS), 512, HAT_SMEM>>>(wcap);
    k_adj<<<dim3(2, BB), 512, ADJ_SMEM>>>(mask, out_adj);
    k_route<<<BB, 512, ROUT_SMEM>>>(mask, out_cap);
}